// round 1
// baseline (speedup 1.0000x reference)
#include <cuda_runtime.h>
#include <cuda_bf16.h>

#define TPB    64
#define ROWF   60          // floats per row
#define STR    61          // smem row stride (odd -> bank-conflict-free)
#define NSTEP  10

__device__ float g_partials[8192];

// ---------------------------------------------------------------------------
// fast atan2: max abs err ~1e-5 rad. Rotation terms carry ~1e-5 of the loss
// mass (translation terms are ~1e6 vs rotation <= pi^2), so this is far
// inside the 1e-3 rel-err budget.
// ---------------------------------------------------------------------------
__device__ __forceinline__ float fast_atan2f(float y, float x) {
    float ax = fabsf(x), ay = fabsf(y);
    float mx = fmaxf(ax, ay);
    float mn = fminf(ax, ay);
    float a  = __fdividef(mn, mx);
    float s  = a * a;
    float r  = fmaf(0.024840285f, s, -0.11643287f);
    r = fmaf(r, s, 0.19354346f);
    r = fmaf(r, s, -0.33262348f);
    r = fmaf(r, s, 0.99997726f);
    r = a * r;                       // atan(a), a in [0,1]
    if (ay > ax)   r = 1.57079632679489662f - r;
    if (x < 0.0f)  r = 3.14159265358979323f - r;
    return copysignf(r, y);
}

__device__ __forceinline__ void euler_to_mat(float x, float y, float z, float* R) {
    float cx, sx, cy, sy, cz, sz;
    __sincosf(x, &sx, &cx);
    __sincosf(y, &sy, &cy);
    __sincosf(z, &sz, &cz);
    R[0] = cz * cy;
    R[1] = cz * sy * sx - sz * cx;
    R[2] = cz * sy * cx + sz * sx;
    R[3] = sz * cy;
    R[4] = sz * sy * sx + cz * cx;
    R[5] = sz * sy * cx - cz * sx;
    R[6] = -sy;
    R[7] = cy * sx;
    R[8] = cy * cx;
}

// matrix_to_euler from the 7 entries actually used
__device__ __forceinline__ void mat_to_euler(
    float M00, float M10, float M20, float M21, float M22,
    float M11, float M12, float* e)
{
    float sy = sqrtf(M00 * M00 + M10 * M10);
    bool sing = sy < 1e-6f;
    e[0] = sing ? fast_atan2f(-M12, M11) : fast_atan2f(M21, M22);
    e[1] = fast_atan2f(-M20, sy);
    e[2] = sing ? 0.0f : fast_atan2f(M10, M00);
}

__global__ void __launch_bounds__(TPB)
cycle_loss_kernel(const float* __restrict__ pred, const float* __restrict__ gt)
{
    __shared__ float sp[TPB * STR];
    __shared__ float sg[TPB * STR];
    const int tid = threadIdx.x;

    // ---- coalesced float4 stage into smem (odd stride 61) ----
    {
        long base = (long)blockIdx.x * TPB * ROWF;
        const float4* p4 = (const float4*)(pred + base);
        const float4* g4 = (const float4*)(gt + base);
        #pragma unroll
        for (int j = tid; j < TPB * (ROWF / 4); j += TPB) {
            int r = j / 15;
            int c = (j % 15) * 4;
            float4 v = p4[j];
            float* d = &sp[r * STR + c];
            d[0] = v.x; d[1] = v.y; d[2] = v.z; d[3] = v.w;
            float4 w = g4[j];
            float* d2 = &sg[r * STR + c];
            d2[0] = w.x; d2[1] = w.y; d2[2] = w.z; d2[3] = w.w;
        }
    }
    __syncthreads();

    const float* P = &sp[tid * STR];
    const float* G = &sg[tid * STR];

    float acc = 0.0f;

    // ---------------- translation part ----------------
    // v[0] = t0 ; v[i] = 2*v[i-1] + sum_{k=1}^{i-1} t[k]
    {
        float vp0 = P[0], vp1 = P[1], vp2 = P[2];
        float vg0 = G[0], vg1 = G[1], vg2 = G[2];
        float d0 = vp0 - vg0, d1 = vp1 - vg1, d2 = vp2 - vg2;
        acc += d0 * d0 + d1 * d1 + d2 * d2;
        float cp0 = 0.f, cp1 = 0.f, cp2 = 0.f;
        float cg0 = 0.f, cg1 = 0.f, cg2 = 0.f;
        for (int i = 1; i < NSTEP; i++) {
            vp0 = 2.0f * vp0 + cp0;
            vp1 = 2.0f * vp1 + cp1;
            vp2 = 2.0f * vp2 + cp2;
            vg0 = 2.0f * vg0 + cg0;
            vg1 = 2.0f * vg1 + cg1;
            vg2 = 2.0f * vg2 + cg2;
            d0 = vp0 - vg0; d1 = vp1 - vg1; d2 = vp2 - vg2;
            acc += d0 * d0 + d1 * d1 + d2 * d2;
            const float* tp = &P[i * 6];
            const float* tg = &G[i * 6];
            cp0 += tp[0]; cp1 += tp[1]; cp2 += tp[2];
            cg0 += tg[0]; cg1 += tg[1]; cg2 += tg[2];
        }
    }

    // ---------------- rotation part ----------------
    // M[i] = R[1] .* prod_{k<i} R[k]   (all elementwise), rot[i]=mat_to_euler(M[i])
    {
        float R1p[9], R1g[9];
        euler_to_mat(P[9],  P[10], P[11], R1p);   // step 1 euler = row[6+3..5]
        euler_to_mat(G[9],  G[10], G[11], R1g);

        float pp[9], pg[9];
        #pragma unroll
        for (int k = 0; k < 9; k++) { pp[k] = 1.0f; pg[k] = 1.0f; }

        for (int i = 0; i < NSTEP; i++) {
            float ep[3], eg[3];
            mat_to_euler(R1p[0] * pp[0], R1p[3] * pp[3], R1p[6] * pp[6],
                         R1p[7] * pp[7], R1p[8] * pp[8],
                         R1p[4] * pp[4], R1p[5] * pp[5], ep);
            mat_to_euler(R1g[0] * pg[0], R1g[3] * pg[3], R1g[6] * pg[6],
                         R1g[7] * pg[7], R1g[8] * pg[8],
                         R1g[4] * pg[4], R1g[5] * pg[5], eg);
            float d0 = ep[0] - eg[0];
            float d1 = ep[1] - eg[1];
            float d2 = ep[2] - eg[2];
            acc += d0 * d0 + d1 * d1 + d2 * d2;

            if (i < NSTEP - 1) {            // last update unused
                float Rp[9], Rg[9];
                euler_to_mat(P[i * 6 + 3], P[i * 6 + 4], P[i * 6 + 5], Rp);
                euler_to_mat(G[i * 6 + 3], G[i * 6 + 4], G[i * 6 + 5], Rg);
                #pragma unroll
                for (int k = 0; k < 9; k++) { pp[k] *= Rp[k]; pg[k] *= Rg[k]; }
            }
        }
    }

    // ---------------- block reduction ----------------
    #pragma unroll
    for (int o = 16; o > 0; o >>= 1)
        acc += __shfl_down_sync(0xffffffffu, acc, o);

    __shared__ float wsum[TPB / 32];
    if ((tid & 31) == 0) wsum[tid >> 5] = acc;
    __syncthreads();
    if (tid == 0) {
        float s = 0.0f;
        #pragma unroll
        for (int w = 0; w < TPB / 32; w++) s += wsum[w];
        g_partials[blockIdx.x] = s;
    }
}

__global__ void __launch_bounds__(1024)
final_reduce_kernel(float* __restrict__ out, int n, double scale)
{
    const int tid = threadIdx.x;
    double s = 0.0;
    for (int i = tid; i < n; i += 1024)
        s += (double)g_partials[i];
    #pragma unroll
    for (int o = 16; o > 0; o >>= 1)
        s += __shfl_down_sync(0xffffffffu, s, o);
    __shared__ double wsum[32];
    if ((tid & 31) == 0) wsum[tid >> 5] = s;
    __syncthreads();
    if (tid == 0) {
        double t = 0.0;
        #pragma unroll
        for (int w = 0; w < 32; w++) t += wsum[w];
        out[0] = (float)(t * scale);
    }
}

extern "C" void kernel_launch(void* const* d_in, const int* in_sizes, int n_in,
                              void* d_out, int out_size)
{
    const float* pred = (const float*)d_in[0];
    const float* gt   = (const float*)d_in[1];
    int batch   = in_sizes[0] / ROWF;       // 262144
    int nblocks = batch / TPB;              // 4096

    cycle_loss_kernel<<<nblocks, TPB>>>(pred, gt);

    // loss = mean over (B,10,2,3) / B  = sum / (60 * B * B)
    double scale = 1.0 / (60.0 * (double)batch * (double)batch);
    final_reduce_kernel<<<1, 1024>>>((float*)d_out, nblocks, scale);
}